// round 1
// baseline (speedup 1.0000x reference)
#include <cuda_runtime.h>
#include <math.h>

#define NB   8
#define SEQ  4096
#define DIM  256

// scratch for projected q, k, v (static device arrays: allocation-guard safe)
__device__ float g_q[NB * SEQ * DIM];
__device__ float g_k[NB * SEQ * DIM];
__device__ float g_v[NB * SEQ * DIM];

// ---------------------------------------------------------------------------
// Projection: Out[r][n] = bias[n] + sum_d X[r][d] * W[n][d]   (x @ W.T + b)
// 64x64 output tile per block, K-chunks of 32, d-major smem (stride 68).
// grid = (512 row tiles, 4 col tiles, 3 projections), block = 256 (16x16).
// ---------------------------------------------------------------------------
__global__ __launch_bounds__(256) void proj_kernel(
    const float* __restrict__ query, const float* __restrict__ keys,
    const float* __restrict__ values,
    const float* __restrict__ Wq, const float* __restrict__ bq,
    const float* __restrict__ Wk, const float* __restrict__ bk,
    const float* __restrict__ Wv, const float* __restrict__ bv)
{
    const float *X, *W, *bias;
    float *Out;
    if (blockIdx.z == 0)      { X = query;  W = Wq; bias = bq; Out = g_q; }
    else if (blockIdx.z == 1) { X = keys;   W = Wk; bias = bk; Out = g_k; }
    else                      { X = values; W = Wv; bias = bv; Out = g_v; }

    __shared__ __align__(16) float Xs[32][68];
    __shared__ __align__(16) float Ws[32][68];

    const int tid = threadIdx.x;
    const int tx = tid & 15, ty = tid >> 4;
    const int r0 = blockIdx.x * 64;
    const int n0 = blockIdx.y * 64;

    float acc[4][4] = {};

    for (int dc = 0; dc < DIM; dc += 32) {
        __syncthreads();
#pragma unroll
        for (int u = 0; u < 2; u++) {
            int idx = tid + u * 256;          // 0..511
            int e   = idx & 1;
            int row = (idx >> 1) & 63;
            int dq  = (idx >> 7) * 2 + e;     // 0..7
            float4 xv = *reinterpret_cast<const float4*>(
                &X[(size_t)(r0 + row) * DIM + dc + dq * 4]);
            Xs[dq * 4 + 0][row] = xv.x; Xs[dq * 4 + 1][row] = xv.y;
            Xs[dq * 4 + 2][row] = xv.z; Xs[dq * 4 + 3][row] = xv.w;
            float4 wv = *reinterpret_cast<const float4*>(
                &W[(size_t)(n0 + row) * DIM + dc + dq * 4]);
            Ws[dq * 4 + 0][row] = wv.x; Ws[dq * 4 + 1][row] = wv.y;
            Ws[dq * 4 + 2][row] = wv.z; Ws[dq * 4 + 3][row] = wv.w;
        }
        __syncthreads();
#pragma unroll
        for (int dl = 0; dl < 32; dl++) {
            float4 a = *reinterpret_cast<const float4*>(&Xs[dl][ty * 4]);
            float4 b = *reinterpret_cast<const float4*>(&Ws[dl][tx * 4]);
            float av[4] = {a.x, a.y, a.z, a.w};
            float bv4[4] = {b.x, b.y, b.z, b.w};
#pragma unroll
            for (int i = 0; i < 4; i++)
#pragma unroll
                for (int j = 0; j < 4; j++)
                    acc[i][j] += av[i] * bv4[j];
        }
    }

#pragma unroll
    for (int i = 0; i < 4; i++) {
        size_t r = (size_t)(r0 + ty * 4 + i);
        float4 o;
        o.x = acc[i][0] + bias[n0 + tx * 4 + 0];
        o.y = acc[i][1] + bias[n0 + tx * 4 + 1];
        o.z = acc[i][2] + bias[n0 + tx * 4 + 2];
        o.w = acc[i][3] + bias[n0 + tx * 4 + 3];
        *reinterpret_cast<float4*>(&Out[r * DIM + n0 + tx * 4]) = o;
    }
}

// ---------------------------------------------------------------------------
// Flash attention (fp32). Block = 256 threads (16x16), 64-query tile,
// iterates over 64-key tiles with online softmax.
//   Qs, Ks: d-major [256][68]   Vs: row-major [64][260]   Ps: [64][68]
// Thread (tx,ty): score rows qi=4ty+i, score cols kj=4tx+j,
//                 O cols d = 4tx + 64j (j=0..3), O rows qi.
// ---------------------------------------------------------------------------
#define SMEM_FLOATS (256 * 68 * 2 + 64 * 260 + 64 * 68)
#define SMEM_BYTES  (SMEM_FLOATS * 4)

__global__ __launch_bounds__(256) void attn_kernel(float* __restrict__ out)
{
    extern __shared__ __align__(16) float smem[];
    float* Qs = smem;                 // [256][68] d-major
    float* Ks = Qs + 256 * 68;        // [256][68] d-major
    float* Vs = Ks + 256 * 68;        // [64][260] row-major
    float* Ps = Vs + 64 * 260;        // [64][68]

    const int tid = threadIdx.x;
    const int tx = tid & 15, ty = tid >> 4;
    const int b  = blockIdx.y;
    const int q0 = blockIdx.x * 64;

    const float* Qg = g_q + ((size_t)b * SEQ + q0) * DIM;
    const float* Kg = g_k + (size_t)b * SEQ * DIM;
    const float* Vg = g_v + (size_t)b * SEQ * DIM;

    // Load Q tile into d-major smem. Lane-pair mapping keeps transposed STS
    // conflict-free (banks = 16e + 4c + row cover all 32).
#pragma unroll
    for (int u = 0; u < 16; u++) {
        int idx = tid + u * 256;          // 0..4095
        int e   = idx & 1;
        int row = (idx >> 1) & 63;
        int c4  = (idx >> 7) * 2 + e;     // 0..63
        float4 v = *reinterpret_cast<const float4*>(&Qg[(size_t)row * DIM + c4 * 4]);
        Qs[(c4 * 4 + 0) * 68 + row] = v.x;
        Qs[(c4 * 4 + 1) * 68 + row] = v.y;
        Qs[(c4 * 4 + 2) * 68 + row] = v.z;
        Qs[(c4 * 4 + 3) * 68 + row] = v.w;
    }

    float o[4][16] = {};
    float m[4], l[4];
#pragma unroll
    for (int i = 0; i < 4; i++) { m[i] = -1e30f; l[i] = 0.f; }

    for (int k0 = 0; k0 < SEQ; k0 += 64) {
        __syncthreads();   // previous P·V finished reading Vs/Ps

        // K tile (d-major, transposed store)
#pragma unroll
        for (int u = 0; u < 16; u++) {
            int idx = tid + u * 256;
            int e   = idx & 1;
            int row = (idx >> 1) & 63;
            int c4  = (idx >> 7) * 2 + e;
            float4 v = *reinterpret_cast<const float4*>(
                &Kg[(size_t)(k0 + row) * DIM + c4 * 4]);
            Ks[(c4 * 4 + 0) * 68 + row] = v.x;
            Ks[(c4 * 4 + 1) * 68 + row] = v.y;
            Ks[(c4 * 4 + 2) * 68 + row] = v.z;
            Ks[(c4 * 4 + 3) * 68 + row] = v.w;
        }
        // V tile (straight float4 copy)
#pragma unroll
        for (int u = 0; u < 16; u++) {
            int idx = tid + u * 256;
            int row = idx >> 6;
            int c4  = idx & 63;
            *reinterpret_cast<float4*>(&Vs[row * 260 + c4 * 4]) =
                *reinterpret_cast<const float4*>(
                    &Vg[(size_t)(k0 + row) * DIM + c4 * 4]);
        }
        __syncthreads();

        // ---- scores: S[qi][kj] = Q[qi] . K[kj]  (no 1/sqrt(d) scaling) ----
        float s[4][4] = {};
#pragma unroll 8
        for (int dl = 0; dl < DIM; dl++) {
            float4 a = *reinterpret_cast<const float4*>(&Qs[dl * 68 + ty * 4]);
            float4 bb = *reinterpret_cast<const float4*>(&Ks[dl * 68 + tx * 4]);
            float av[4] = {a.x, a.y, a.z, a.w};
            float bv4[4] = {bb.x, bb.y, bb.z, bb.w};
#pragma unroll
            for (int i = 0; i < 4; i++)
#pragma unroll
                for (int j = 0; j < 4; j++)
                    s[i][j] += av[i] * bv4[j];
        }

        // ---- online softmax (row reduce over 16-lane groups) ----
#pragma unroll
        for (int i = 0; i < 4; i++) {
            float mx = fmaxf(fmaxf(s[i][0], s[i][1]), fmaxf(s[i][2], s[i][3]));
#pragma unroll
            for (int off = 1; off < 16; off <<= 1)
                mx = fmaxf(mx, __shfl_xor_sync(0xffffffffu, mx, off));
            float mn   = fmaxf(m[i], mx);
            float corr = __expf(m[i] - mn);
            float p0 = __expf(s[i][0] - mn);
            float p1 = __expf(s[i][1] - mn);
            float p2 = __expf(s[i][2] - mn);
            float p3 = __expf(s[i][3] - mn);
            float rs = (p0 + p1) + (p2 + p3);
#pragma unroll
            for (int off = 1; off < 16; off <<= 1)
                rs += __shfl_xor_sync(0xffffffffu, rs, off);
            l[i] = l[i] * corr + rs;
            m[i] = mn;
            *reinterpret_cast<float4*>(&Ps[(ty * 4 + i) * 68 + tx * 4]) =
                make_float4(p0, p1, p2, p3);
#pragma unroll
            for (int c = 0; c < 16; c++) o[i][c] *= corr;
        }
        __syncthreads();   // Ps visible to all

        // ---- O += P . V ----
#pragma unroll 4
        for (int k = 0; k < 64; k++) {
            float p[4];
#pragma unroll
            for (int i = 0; i < 4; i++) p[i] = Ps[(ty * 4 + i) * 68 + k];
            const float4* Vrow = reinterpret_cast<const float4*>(&Vs[k * 260]);
#pragma unroll
            for (int j = 0; j < 4; j++) {
                float4 vv = Vrow[tx + 16 * j];
#pragma unroll
                for (int i = 0; i < 4; i++) {
                    o[i][4 * j + 0] += p[i] * vv.x;
                    o[i][4 * j + 1] += p[i] * vv.y;
                    o[i][4 * j + 2] += p[i] * vv.z;
                    o[i][4 * j + 3] += p[i] * vv.w;
                }
            }
        }
    }

    // ---- normalize + store ----
#pragma unroll
    for (int i = 0; i < 4; i++) {
        float inv = 1.f / l[i];
        size_t rbase = ((size_t)b * SEQ + q0 + ty * 4 + i) * DIM;
#pragma unroll
        for (int j = 0; j < 4; j++) {
            float4 ov;
            ov.x = o[i][4 * j + 0] * inv;
            ov.y = o[i][4 * j + 1] * inv;
            ov.z = o[i][4 * j + 2] * inv;
            ov.w = o[i][4 * j + 3] * inv;
            *reinterpret_cast<float4*>(&out[rbase + 4 * tx + 64 * j]) = ov;
        }
    }
}

// ---------------------------------------------------------------------------
extern "C" void kernel_launch(void* const* d_in, const int* in_sizes, int n_in,
                              void* d_out, int out_size)
{
    (void)in_sizes; (void)n_in; (void)out_size;
    const float* query  = (const float*)d_in[0];
    const float* keys   = (const float*)d_in[1];
    const float* values = (const float*)d_in[2];
    const float* Wq     = (const float*)d_in[3];
    const float* bq     = (const float*)d_in[4];
    const float* Wk     = (const float*)d_in[5];
    const float* bk     = (const float*)d_in[6];
    const float* Wv     = (const float*)d_in[7];
    const float* bv     = (const float*)d_in[8];
    float* out = (float*)d_out;

    cudaFuncSetAttribute(attn_kernel,
                         cudaFuncAttributeMaxDynamicSharedMemorySize, SMEM_BYTES);

    proj_kernel<<<dim3((NB * SEQ) / 64, DIM / 64, 3), 256>>>(
        query, keys, values, Wq, bq, Wk, bk, Wv, bv);
    attn_kernel<<<dim3(SEQ / 64, NB), 256, SMEM_BYTES>>>(out);
}

// round 5
// speedup vs baseline: 3.8065x; 3.8065x over previous
#include <cuda_runtime.h>
#include <cuda_bf16.h>
#include <stdint.h>

#define NBATCH 8
#define SEQ    4096
#define DIM    256
#define NTOK   (NBATCH * SEQ)                 // 32768
#define PROJ_ELEMS (NTOK * DIM)               // 8388608
#define BCHUNK 2
#define SCHUNK_ELEMS ((long long)BCHUNK * SEQ * SEQ)   // 33554432 floats

// ---------------- scratch (static device arrays) ---------------------------
// g_S: BCHUNK batches of fp32 scores; softmax overwrites each 4096-float row
// in place with 4096 hi-bf16 + 4096 lo-bf16 of normalized P.
__device__ __align__(16) float          g_S[SCHUNK_ELEMS];            // 134 MB
__device__ __align__(16) unsigned short g_wh[3][DIM * DIM];
__device__ __align__(16) unsigned short g_wl[3][DIM * DIM];
__device__ __align__(16) unsigned short g_qh[PROJ_ELEMS], g_ql[PROJ_ELEMS];
__device__ __align__(16) unsigned short g_kh[PROJ_ELEMS], g_kl[PROJ_ELEMS];
__device__ __align__(16) unsigned short g_vth[PROJ_ELEMS], g_vtl[PROJ_ELEMS];

// ---------------- helpers ---------------------------------------------------
__device__ __forceinline__ uint32_t smem_u32(const void* p) {
    uint32_t a;
    asm("{ .reg .u64 t; cvta.to.shared.u64 t, %1; cvt.u32.u64 %0, t; }"
        : "=r"(a) : "l"(p));
    return a;
}

#define CP16(dst, src) \
    asm volatile("cp.async.cg.shared.global [%0], [%1], 16;" \
                 :: "r"(dst), "l"(src) : "memory")
#define CP_COMMIT()  asm volatile("cp.async.commit_group;" ::: "memory")
#define CP_WAIT1()   asm volatile("cp.async.wait_group 1;" ::: "memory")
#define CP_WAIT0()   asm volatile("cp.async.wait_group 0;" ::: "memory")

#define LDSM4(r, addr) \
    asm volatile("ldmatrix.sync.aligned.m8n8.x4.shared.b16 {%0,%1,%2,%3}, [%4];" \
                 : "=r"((r)[0]), "=r"((r)[1]), "=r"((r)[2]), "=r"((r)[3]) \
                 : "r"(addr))

#define MMA(d, a, b) \
    asm volatile("mma.sync.aligned.m16n8k16.row.col.f32.bf16.bf16.f32 " \
                 "{%0,%1,%2,%3},{%4,%5,%6,%7},{%8,%9},{%0,%1,%2,%3};" \
                 : "+f"((d)[0]), "+f"((d)[1]), "+f"((d)[2]), "+f"((d)[3]) \
                 : "r"((a)[0]), "r"((a)[1]), "r"((a)[2]), "r"((a)[3]), \
                   "r"((b)[0]), "r"((b)[1]))

__device__ __forceinline__ void split_bf(float x, unsigned short& h, unsigned short& l) {
    __nv_bfloat16 hb = __float2bfloat16_rn(x);
    float r = x - __bfloat162float(hb);
    __nv_bfloat16 lb = __float2bfloat16_rn(r);
    h = __bfloat16_as_ushort(hb);
    l = __bfloat16_as_ushort(lb);
}

// smem tile layout: [128 rows][64 bf16] = 128B rows, SW128-style chunk XOR.
// byte offset of (r, k): r*128 + ((k*2) ^ ((r&7)<<4))
#define TSZ   16384                 // one tile-split (128 x 64 bf16)
#define STAGE_BYTES (4 * TSZ)       // Ah, Al, Bh, Bl
#define NSTAGE 3
#define SMEM_TOTAL (NSTAGE * STAGE_BYTES)   // 196608

// ---------------------------------------------------------------------------
// Split-bf16 mma.sync GEMM.  C[m][n] = sum_k (Ah+Al)[m][k]*(Bh+Bl)[n][k]
// Block tile 128x128, warp tile 32x64, K chunks of 64, 3-stage cp.async.
//   CFG 0/1: projection q/k. A = fp32 input (split in staging), B = W.
//            Epilogue: +bias, split -> g_qh/g_ql or g_kh/g_kl.
//   CFG 2:   projection v, transposed epilogue -> g_vth/g_vtl [b][d][sq].
//   CFG 3:   scores: A=q, B=k (batch zbase+z), fp32 -> g_S[z].
//   CFG 4:   context: A = P hi/lo rows in g_S (ld 8192, lo at +4096),
//            B = vt, fp32 -> Cf.
// ---------------------------------------------------------------------------
template<int CFG>
__global__ __launch_bounds__(256, 1)
void gemm_kernel(const float* __restrict__ Af, float* __restrict__ Cf,
                 const float* __restrict__ bias, int zbase)
{
    constexpr int  K    = (CFG == 4) ? 4096 : 256;
    constexpr int  NC   = K / 64;
    constexpr bool AF32 = (CFG <= 2);
    constexpr int  LDA  = (CFG == 4) ? 8192 : 256;
    constexpr int  LDB  = (CFG == 4) ? 4096 : 256;

    extern __shared__ __align__(128) char sm[];
    const uint32_t smb = smem_u32(sm);
    const int tid = threadIdx.x;
    const int w = tid >> 5, lane = tid & 31;
    const int wm = w & 3, wn = w >> 2;
    const int m0 = blockIdx.x * 128, n0 = blockIdx.y * 128;
    const int z = blockIdx.z;

    const float* Afp = nullptr;
    const unsigned short *Ahp = nullptr, *Alp = nullptr, *Bhp = nullptr, *Blp = nullptr;
    if (CFG <= 2) {
        Afp = Af + (long long)m0 * 256;
        Bhp = g_wh[CFG] + n0 * 256;
        Blp = g_wl[CFG] + n0 * 256;
    } else if (CFG == 3) {
        long long b = zbase + z;
        Ahp = g_qh + (b * SEQ + m0) * 256;
        Alp = g_ql + (b * SEQ + m0) * 256;
        Bhp = g_kh + (b * SEQ + n0) * 256;
        Blp = g_kl + (b * SEQ + n0) * 256;
    } else {
        long long b = zbase + z;
        Ahp = reinterpret_cast<const unsigned short*>(g_S)
              + (long long)z * SEQ * 8192 + (long long)m0 * 8192;
        Alp = Ahp + 4096;
        Bhp = g_vth + b * (long long)DIM * SEQ + (long long)n0 * 4096;
        Blp = g_vtl + b * (long long)DIM * SEQ + (long long)n0 * 4096;
    }

    float acc[2][8][4] = {};

    auto stage = [&](int c) {
        const int buf = c % NSTAGE;
        const uint32_t sb = smb + buf * STAGE_BYTES;
        char* sbp = sm + buf * STAGE_BYTES;
        const int k0 = c * 64;
        if (AF32) {
            // A fp32 -> hi/lo bf16 during staging (manual STS)
#pragma unroll
            for (int t = tid; t < 2048; t += 256) {
                int r = t >> 4, kq = (t & 15) * 4;
                float4 v = *reinterpret_cast<const float4*>(Afp + r * LDA + k0 + kq);
                ushort4 hh, ll;
                split_bf(v.x, hh.x, ll.x); split_bf(v.y, hh.y, ll.y);
                split_bf(v.z, hh.z, ll.z); split_bf(v.w, hh.w, ll.w);
                int off = r * 128 + ((kq * 2) ^ ((r & 7) << 4));
                *reinterpret_cast<ushort4*>(sbp + off)       = hh;
                *reinterpret_cast<ushort4*>(sbp + TSZ + off) = ll;
            }
#pragma unroll
            for (int t = tid; t < 2048; t += 256) {
                int ts = t >> 10, r = (t >> 3) & 127, kc = (t & 7) << 3;
                const unsigned short* src = (ts ? Blp : Bhp) + r * LDB + k0 + kc;
                uint32_t d = sb + (2 + ts) * TSZ + r * 128 + ((kc * 2) ^ ((r & 7) << 4));
                CP16(d, src);
            }
        } else {
#pragma unroll
            for (int t = tid; t < 4096; t += 256) {
                int ts = t >> 10, r = (t >> 3) & 127, kc = (t & 7) << 3;
                const unsigned short* src =
                    (ts == 0 ? Ahp : ts == 1 ? Alp : ts == 2 ? Bhp : Blp)
                    + r * (ts < 2 ? LDA : LDB) + k0 + kc;
                uint32_t d = sb + ts * TSZ + r * 128 + ((kc * 2) ^ ((r & 7) << 4));
                CP16(d, src);
            }
        }
        CP_COMMIT();
    };

    // per-thread ldmatrix row/col constants
    const int a_r0 = wm * 32 + (lane & 7) + ((lane >> 3) & 1) * 8;   // + mt*16
    const int a_kb = (lane >> 4) * 16;                                // byte
    const int b_n0 = wn * 64 + (lane & 7) + (lane >> 4) * 8;          // + g*16
    const int b_kb = ((lane >> 3) & 1) * 16;                          // byte

    auto compute = [&](int buf) {
        const uint32_t sb = smb + buf * STAGE_BYTES;
#pragma unroll
        for (int ks = 0; ks < 4; ks++) {
            uint32_t Ahf[2][4], Alf[2][4], Bhf[4][4], Blf[4][4];
#pragma unroll
            for (int mt = 0; mt < 2; mt++) {
                int row = a_r0 + mt * 16;
                int kb = ks * 32 + a_kb;
                uint32_t ad = sb + row * 128 + (kb ^ ((row & 7) << 4));
                LDSM4(Ahf[mt], ad);
                LDSM4(Alf[mt], ad + TSZ);
            }
#pragma unroll
            for (int g = 0; g < 4; g++) {
                int nrow = b_n0 + g * 16;
                int kb = ks * 32 + b_kb;
                uint32_t bd = sb + 2 * TSZ + nrow * 128 + (kb ^ ((nrow & 7) << 4));
                LDSM4(Bhf[g], bd);
                LDSM4(Blf[g], bd + TSZ);
            }
#pragma unroll
            for (int mt = 0; mt < 2; mt++)
#pragma unroll
                for (int g = 0; g < 4; g++)
#pragma unroll
                    for (int sub = 0; sub < 2; sub++) {
                        int nt = g * 2 + sub;
                        MMA(acc[mt][nt], Ahf[mt], Bhf[g] + sub * 2);   // hi*hi
                        MMA(acc[mt][nt], Ahf[mt], Blf[g] + sub * 2);   // hi*lo
                        MMA(acc[mt][nt], Alf[mt], Bhf[g] + sub * 2);   // lo*hi
                    }
        }
    };

    stage(0);
    stage(1);
    for (int c = 0; c < NC; c++) {
        if (c < NC - 1) CP_WAIT1(); else CP_WAIT0();
        __syncthreads();
        if (c + 2 < NC) stage(c + 2);
        compute(c % NSTAGE);
    }
    __syncthreads();

    // ---------------- epilogue ----------------
    if (CFG == 0 || CFG == 1) {
        unsigned short* DH = (CFG == 0) ? g_qh : g_kh;
        unsigned short* DL = (CFG == 0) ? g_ql : g_kl;
#pragma unroll
        for (int mt = 0; mt < 2; mt++)
#pragma unroll
            for (int nt = 0; nt < 8; nt++) {
                int m = m0 + wm * 32 + mt * 16 + (lane >> 2);
                int ng = n0 + wn * 64 + nt * 8 + (lane & 3) * 2;
                float b0 = bias[ng], b1 = bias[ng + 1];
                float* a = acc[mt][nt];
                ushort2 h2, l2;
                split_bf(a[0] + b0, h2.x, l2.x); split_bf(a[1] + b1, h2.y, l2.y);
                *reinterpret_cast<ushort2*>(&DH[(long long)m * 256 + ng]) = h2;
                *reinterpret_cast<ushort2*>(&DL[(long long)m * 256 + ng]) = l2;
                split_bf(a[2] + b0, h2.x, l2.x); split_bf(a[3] + b1, h2.y, l2.y);
                *reinterpret_cast<ushort2*>(&DH[(long long)(m + 8) * 256 + ng]) = h2;
                *reinterpret_cast<ushort2*>(&DL[(long long)(m + 8) * 256 + ng]) = l2;
            }
    } else if (CFG == 2) {
        // transpose through smem: Cs[128 m][132 pitch]
        float* Cs = reinterpret_cast<float*>(sm);
#pragma unroll
        for (int mt = 0; mt < 2; mt++)
#pragma unroll
            for (int nt = 0; nt < 8; nt++) {
                int ml = wm * 32 + mt * 16 + (lane >> 2);
                int nl = wn * 64 + nt * 8 + (lane & 3) * 2;
                float b0 = bias[n0 + nl], b1 = bias[n0 + nl + 1];
                float* a = acc[mt][nt];
                *reinterpret_cast<float2*>(&Cs[ml * 132 + nl])
                    = make_float2(a[0] + b0, a[1] + b1);
                *reinterpret_cast<float2*>(&Cs[(ml + 8) * 132 + nl])
                    = make_float2(a[2] + b0, a[3] + b1);
            }
        __syncthreads();
        int nl = tid >> 1, half = tid & 1;
        long long bb = m0 >> 12;
        int sqb = (m0 & 4095) + half * 64;
        long long obase = bb * (long long)DIM * SEQ
                        + (long long)(n0 + nl) * SEQ + sqb;
#pragma unroll
        for (int j = 0; j < 16; j++) {
            int ml = half * 64 + j * 4;
            ushort4 hh, ll;
            split_bf(Cs[(ml + 0) * 132 + nl], hh.x, ll.x);
            split_bf(Cs[(ml + 1) * 132 + nl], hh.y, ll.y);
            split_bf(Cs[(ml + 2) * 132 + nl], hh.z, ll.z);
            split_bf(Cs[(ml + 3) * 132 + nl], hh.w, ll.w);
            *reinterpret_cast<ushort4*>(&g_vth[obase + j * 4]) = hh;
            *reinterpret_cast<ushort4*>(&g_vtl[obase + j * 4]) = ll;
        }
    } else if (CFG == 3) {
#pragma unroll
        for (int mt = 0; mt < 2; mt++)
#pragma unroll
            for (int nt = 0; nt < 8; nt++) {
                int m = m0 + wm * 32 + mt * 16 + (lane >> 2);
                int n = n0 + wn * 64 + nt * 8 + (lane & 3) * 2;
                float* a = acc[mt][nt];
                long long base = (long long)z * SEQ * SEQ;
                *reinterpret_cast<float2*>(&g_S[base + (long long)m * 4096 + n])
                    = make_float2(a[0], a[1]);
                *reinterpret_cast<float2*>(&g_S[base + (long long)(m + 8) * 4096 + n])
                    = make_float2(a[2], a[3]);
            }
    } else {
#pragma unroll
        for (int mt = 0; mt < 2; mt++)
#pragma unroll
            for (int nt = 0; nt < 8; nt++) {
                int m = m0 + wm * 32 + mt * 16 + (lane >> 2);
                int n = n0 + wn * 64 + nt * 8 + (lane & 3) * 2;
                float* a = acc[mt][nt];
                long long rb = ((long long)(zbase + z) * SEQ + m) * 256 + n;
                *reinterpret_cast<float2*>(&Cf[rb])       = make_float2(a[0], a[1]);
                *reinterpret_cast<float2*>(&Cf[rb + 2048]) = make_float2(a[2], a[3]);
            }
    }
}

// ---------------------------------------------------------------------------
// weight split: fp32 W[I] -> g_wh[I]/g_wl[I]
// ---------------------------------------------------------------------------
template<int I>
__global__ __launch_bounds__(256) void split_w_kernel(const float* __restrict__ x)
{
    int i = blockIdx.x * 256 + threadIdx.x;    // 16384 float4 groups
    float4 v = reinterpret_cast<const float4*>(x)[i];
    ushort4 hh, ll;
    split_bf(v.x, hh.x, ll.x);
    split_bf(v.y, hh.y, ll.y);
    split_bf(v.z, hh.z, ll.z);
    split_bf(v.w, hh.w, ll.w);
    reinterpret_cast<ushort4*>(g_wh[I])[i] = hh;
    reinterpret_cast<ushort4*>(g_wl[I])[i] = ll;
}

// ---------------------------------------------------------------------------
// softmax over rows of 4096 in g_S, IN PLACE: fp32 row -> hi bf16 (first
// 8KB) + lo bf16 (second 8KB) of normalized P.
// ---------------------------------------------------------------------------
__global__ __launch_bounds__(256, 1) void softmax_kernel()
{
    __shared__ float red[8];
    const int tid = threadIdx.x;
    const int w = tid >> 5, lane = tid & 31;
    float* S = g_S + (long long)blockIdx.x * 4096;

    float4 x[4];
#pragma unroll
    for (int j = 0; j < 4; j++)
        x[j] = *reinterpret_cast<const float4*>(S + (j * 256 + tid) * 4);

    float mx = -1e30f;
#pragma unroll
    for (int j = 0; j < 4; j++)
        mx = fmaxf(mx, fmaxf(fmaxf(x[j].x, x[j].y), fmaxf(x[j].z, x[j].w)));
#pragma unroll
    for (int o = 16; o; o >>= 1) mx = fmaxf(mx, __shfl_xor_sync(~0u, mx, o));
    if (lane == 0) red[w] = mx;
    __syncthreads();
    mx = red[0];
#pragma unroll
    for (int i = 1; i < 8; i++) mx = fmaxf(mx, red[i]);
    __syncthreads();

    float p[16];
    float sum = 0.f;
#pragma unroll
    for (int j = 0; j < 4; j++) {
        p[4 * j + 0] = __expf(x[j].x - mx);
        p[4 * j + 1] = __expf(x[j].y - mx);
        p[4 * j + 2] = __expf(x[j].z - mx);
        p[4 * j + 3] = __expf(x[j].w - mx);
        sum += (p[4 * j] + p[4 * j + 1]) + (p[4 * j + 2] + p[4 * j + 3]);
    }
#pragma unroll
    for (int o = 16; o; o >>= 1) sum += __shfl_xor_sync(~0u, sum, o);
    if (lane == 0) red[w] = sum;
    __syncthreads();
    sum = 0.f;
#pragma unroll
    for (int i = 0; i < 8; i++) sum += red[i];
    float inv = 1.f / sum;
    __syncthreads();   // all reads done; safe to overwrite row

    unsigned short* Ph = reinterpret_cast<unsigned short*>(S);
    unsigned short* Pl = Ph + 4096;
#pragma unroll
    for (int j = 0; j < 4; j++) {
        ushort4 hh, ll;
        split_bf(p[4 * j + 0] * inv, hh.x, ll.x);
        split_bf(p[4 * j + 1] * inv, hh.y, ll.y);
        split_bf(p[4 * j + 2] * inv, hh.z, ll.z);
        split_bf(p[4 * j + 3] * inv, hh.w, ll.w);
        int o = (j * 256 + tid) * 4;
        *reinterpret_cast<ushort4*>(Ph + o) = hh;
        *reinterpret_cast<ushort4*>(Pl + o) = ll;
    }
}

// ---------------------------------------------------------------------------
extern "C" void kernel_launch(void* const* d_in, const int* in_sizes, int n_in,
                              void* d_out, int out_size)
{
    (void)in_sizes; (void)n_in; (void)out_size;
    const float* query  = (const float*)d_in[0];
    const float* keys   = (const float*)d_in[1];
    const float* values = (const float*)d_in[2];
    const float* Wq     = (const float*)d_in[3];
    const float* bq     = (const float*)d_in[4];
    const float* Wk     = (const float*)d_in[5];
    const float* bk     = (const float*)d_in[6];
    const float* Wv     = (const float*)d_in[7];
    const float* bv     = (const float*)d_in[8];
    float* out = (float*)d_out;

    cudaFuncSetAttribute(gemm_kernel<0>, cudaFuncAttributeMaxDynamicSharedMemorySize, SMEM_TOTAL);
    cudaFuncSetAttribute(gemm_kernel<1>, cudaFuncAttributeMaxDynamicSharedMemorySize, SMEM_TOTAL);
    cudaFuncSetAttribute(gemm_kernel<2>, cudaFuncAttributeMaxDynamicSharedMemorySize, SMEM_TOTAL);
    cudaFuncSetAttribute(gemm_kernel<3>, cudaFuncAttributeMaxDynamicSharedMemorySize, SMEM_TOTAL);
    cudaFuncSetAttribute(gemm_kernel<4>, cudaFuncAttributeMaxDynamicSharedMemorySize, SMEM_TOTAL);

    // 1) weight splits
    split_w_kernel<0><<<64, 256>>>(Wq);
    split_w_kernel<1><<<64, 256>>>(Wk);
    split_w_kernel<2><<<64, 256>>>(Wv);

    // 2) projections
    gemm_kernel<0><<<dim3(NTOK / 128, 2, 1), 256, SMEM_TOTAL>>>(query,  nullptr, bq, 0);
    gemm_kernel<1><<<dim3(NTOK / 128, 2, 1), 256, SMEM_TOTAL>>>(keys,   nullptr, bk, 0);
    gemm_kernel<2><<<dim3(NTOK / 128, 2, 1), 256, SMEM_TOTAL>>>(values, nullptr, bv, 0);

    // 3) attention in chunks of BCHUNK batches
    for (int bc = 0; bc < NBATCH / BCHUNK; bc++) {
        gemm_kernel<3><<<dim3(SEQ / 128, SEQ / 128, BCHUNK), 256, SMEM_TOTAL>>>(
            nullptr, nullptr, nullptr, bc * BCHUNK);
        softmax_kernel<<<BCHUNK * SEQ, 256>>>();
        gemm_kernel<4><<<dim3(SEQ / 128, 2, BCHUNK), 256, SMEM_TOTAL>>>(
            nullptr, out, nullptr, bc * BCHUNK);
    }
}